// round 4
// baseline (speedup 1.0000x reference)
#include <cuda_runtime.h>
#include <math.h>

#define D3 (128 * 128 * 128)
#define NSTEPS 111
#define DT 0.03125f

// 64MB scratch: volume re-laid-out as [B, z, y, x] float4 (channels interleaved)
__device__ float4 g_vol[2 * D3];

// ---------------------------------------------------------------------------
// Kernel 1: transpose [B,4,D,D,D] -> [B,D,D,D,4], float4-vectorized
// each thread: 4 consecutive voxels (4x LDG.128 in, 4x STG.128 out)
// ---------------------------------------------------------------------------
__global__ __launch_bounds__(256) void transpose_vol_kernel(const float* __restrict__ vol) {
    int t = blockIdx.x * blockDim.x + threadIdx.x;     // over B*D3/4
    int b = t / (D3 / 4);
    int s4 = (t - b * (D3 / 4)) * 4;
    const float* base = vol + (size_t)b * 4 * D3 + s4;
    float4 c0 = __ldg((const float4*)(base));
    float4 c1 = __ldg((const float4*)(base + D3));
    float4 c2 = __ldg((const float4*)(base + 2 * D3));
    float4 c3 = __ldg((const float4*)(base + 3 * D3));
    float4* o = g_vol + (size_t)b * D3 + s4;
    o[0] = make_float4(c0.x, c1.x, c2.x, c3.x);
    o[1] = make_float4(c0.y, c1.y, c2.y, c3.y);
    o[2] = make_float4(c0.z, c1.z, c2.z, c3.z);
    o[3] = make_float4(c0.w, c1.w, c2.w, c3.w);
}

// ---------------------------------------------------------------------------
// Kernel 2: raymarch (software-pipelined, 2-stage A/B)
// ---------------------------------------------------------------------------
__device__ __forceinline__ float4 lerp4f(float4 a, float4 b, float f) {
    // fma form: a + f*(b-a). Continuous in inputs; not on the bit-exact chain.
    float4 r;
    r.x = fmaf(f, b.x - a.x, a.x);
    r.y = fmaf(f, b.y - a.y, a.y);
    r.z = fmaf(f, b.z - a.z, a.z);
    r.w = fmaf(f, b.w - a.w, a.w);
    return r;
}

struct Stage {
    float4 v0, v1, v2, v3, v4, v5, v6, v7;
    float fx, fy, fz;
    bool valid;
};

// Compute validity + (if valid) fracs and issue the 8 corner loads.
__device__ __forceinline__ void prep_stage(const float4* __restrict__ vol,
                                           float px, float py, float pz,
                                           bool enabled, Stage& S) {
    S.valid = enabled &
              (px > -1.0f) & (px < 1.0f) &
              (py > -1.0f) & (py < 1.0f) &
              (pz > -1.0f) & (pz < 1.0f);
    if (S.valid) {
        // g = clip(((pos+1)*0.5)*(n-1), 0, n-1) — bit-exact op order vs reference
        float gx = fminf(fmaxf(__fmul_rn(__fmul_rn(__fadd_rn(px, 1.0f), 0.5f), 127.0f), 0.0f), 127.0f);
        float gy = fminf(fmaxf(__fmul_rn(__fmul_rn(__fadd_rn(py, 1.0f), 0.5f), 127.0f), 0.0f), 127.0f);
        float gz = fminf(fmaxf(__fmul_rn(__fmul_rn(__fadd_rn(pz, 1.0f), 0.5f), 127.0f), 0.0f), 127.0f);
        int ix = min((int)gx, 126);
        int iy = min((int)gy, 126);
        int iz = min((int)gz, 126);
        S.fx = __fsub_rn(gx, (float)ix);
        S.fy = __fsub_rn(gy, (float)iy);
        S.fz = __fsub_rn(gz, (float)iz);
        const int o = (iz * 128 + iy) * 128 + ix;
        S.v0 = __ldg(vol + o);
        S.v1 = __ldg(vol + o + 1);
        S.v2 = __ldg(vol + o + 128);
        S.v3 = __ldg(vol + o + 129);
        S.v4 = __ldg(vol + o + 16384);
        S.v5 = __ldg(vol + o + 16385);
        S.v6 = __ldg(vol + o + 16512);
        S.v7 = __ldg(vol + o + 16513);
    }
}

// Consume one stage; returns true if the march should stop.
__device__ __forceinline__ bool consume_stage(const Stage& S, bool& entered,
                                              float& accr, float& accg,
                                              float& accb, float& acca) {
    if (S.valid) {
        entered = true;
        float4 c00 = lerp4f(S.v0, S.v1, S.fx);
        float4 c01 = lerp4f(S.v2, S.v3, S.fx);
        float4 c10 = lerp4f(S.v4, S.v5, S.fx);
        float4 c11 = lerp4f(S.v6, S.v7, S.fx);
        float4 c0  = lerp4f(c00, c01, S.fy);
        float4 c1  = lerp4f(c10, c11, S.fy);
        float4 sm  = lerp4f(c0, c1, S.fz);
        const float contrib =
            __fsub_rn(fminf(__fadd_rn(acca, __fmul_rn(sm.w, DT)), 1.0f), acca);
        accr = __fadd_rn(accr, __fmul_rn(sm.x, contrib));
        accg = __fadd_rn(accg, __fmul_rn(sm.y, contrib));
        accb = __fadd_rn(accb, __fmul_rn(sm.z, contrib));
        acca = __fadd_rn(acca, contrib);
        return acca >= 1.0f;          // saturated: contrib == 0 forever
    }
    return entered;                   // convex box: exited for good
}

__global__ __launch_bounds__(256) void raymarch_kernel(
    const float* __restrict__ camrot,     // [B,3,3]
    const float* __restrict__ campos,     // [B,3]
    const float* __restrict__ focal,      // [B,2]
    const float* __restrict__ princpt,    // [B,2]
    const float* __restrict__ pixelcoords,// [B,H,W,2]
    float* __restrict__ out,              // [B,4,H,W]
    int H, int W)
{
    const int w = blockIdx.x * blockDim.x + threadIdx.x;
    const int h = blockIdx.y * blockDim.y + threadIdx.y;
    const int b = blockIdx.z;
    if (w >= W || h >= H) return;

    // ---- ray setup (bit-exact vs JAX: correctly-rounded ops, no FMA) ----
    const float px = pixelcoords[(((size_t)b * H + h) * W + w) * 2 + 0];
    const float py = pixelcoords[(((size_t)b * H + h) * W + w) * 2 + 1];
    const float vx = __fdiv_rn(__fsub_rn(px, princpt[b * 2 + 0]), focal[b * 2 + 0]);
    const float vy = __fdiv_rn(__fsub_rn(py, princpt[b * 2 + 1]), focal[b * 2 + 1]);
    const float vz = 1.0f;

    const float* R = camrot + b * 9;
    float dx = __fadd_rn(__fadd_rn(__fmul_rn(R[0], vx), __fmul_rn(R[3], vy)), __fmul_rn(R[6], vz));
    float dy = __fadd_rn(__fadd_rn(__fmul_rn(R[1], vx), __fmul_rn(R[4], vy)), __fmul_rn(R[7], vz));
    float dz = __fadd_rn(__fadd_rn(__fmul_rn(R[2], vx), __fmul_rn(R[5], vy)), __fmul_rn(R[8], vz));

    const float ss = __fadd_rn(__fadd_rn(__fmul_rn(dx, dx), __fmul_rn(dy, dy)),
                               __fmul_rn(dz, dz));
    const float nrm = __fsqrt_rn(ss);
    dx = __fdiv_rn(dx, nrm);
    dy = __fdiv_rn(dy, nrm);
    dz = __fdiv_rn(dz, nrm);

    const float cx = campos[b * 3 + 0];
    const float cy = campos[b * 3 + 1];
    const float cz = campos[b * 3 + 2];

    // ---- ray-AABB [-1,1]^3, correctly-rounded ----
    const float t1x = __fdiv_rn(__fsub_rn(-1.0f, cx), dx);
    const float t2x = __fdiv_rn(__fsub_rn( 1.0f, cx), dx);
    const float t1y = __fdiv_rn(__fsub_rn(-1.0f, cy), dy);
    const float t2y = __fdiv_rn(__fsub_rn( 1.0f, cy), dy);
    const float t1z = __fdiv_rn(__fsub_rn(-1.0f, cz), dz);
    const float t2z = __fdiv_rn(__fsub_rn( 1.0f, cz), dz);
    const float tmin = fmaxf(fminf(t1x, t2x),
                      fmaxf(fminf(t1y, t2y), fminf(t1z, t2z)));
    const float tmax = fminf(fmaxf(t1x, t2x),
                      fminf(fmaxf(t1y, t2y), fmaxf(t1z, t2z)));
    const bool hit = tmin < tmax;
    const float t0 = fmaxf(hit ? tmin : 0.0f, 0.0f);

    float posx = __fadd_rn(cx, __fmul_rn(dx, t0));
    float posy = __fadd_rn(cy, __fmul_rn(dy, t0));
    float posz = __fadd_rn(cz, __fmul_rn(dz, t0));
    const float sx = __fmul_rn(dx, DT);   // DT = 2^-5: exact
    const float sy = __fmul_rn(dy, DT);
    const float sz = __fmul_rn(dz, DT);

    float accr = 0.0f, accg = 0.0f, accb = 0.0f, acca = 0.0f;

    if (hit) {
        const float4* __restrict__ vol = g_vol + (size_t)b * D3;
        bool entered = false;

        Stage A, B;
        // prologue: step 0 into A
        prep_stage(vol, posx, posy, posz, true, A);

        #pragma unroll 1
        for (int s = 0; s < NSTEPS; s += 2) {
            // advance to step s+1, prefetch into B BEFORE consuming A
            posx = __fadd_rn(posx, sx);
            posy = __fadd_rn(posy, sy);
            posz = __fadd_rn(posz, sz);
            prep_stage(vol, posx, posy, posz, (s + 1) < NSTEPS, B);

            if (consume_stage(A, entered, accr, accg, accb, acca)) break;

            // advance to step s+2, prefetch into A BEFORE consuming B
            posx = __fadd_rn(posx, sx);
            posy = __fadd_rn(posy, sy);
            posz = __fadd_rn(posz, sz);
            prep_stage(vol, posx, posy, posz, (s + 2) < NSTEPS, A);

            if (consume_stage(B, entered, accr, accg, accb, acca)) break;
        }
    }

    const size_t plane = (size_t)H * W;
    const size_t pix = (size_t)h * W + w;
    float* ob = out + (size_t)b * 4 * plane;
    ob[0 * plane + pix] = accr;
    ob[1 * plane + pix] = accg;
    ob[2 * plane + pix] = accb;
    ob[3 * plane + pix] = acca;
}

// ---------------------------------------------------------------------------
// Launch
// ---------------------------------------------------------------------------
extern "C" void kernel_launch(void* const* d_in, const int* in_sizes, int n_in,
                              void* d_out, int out_size) {
    const float* camrot      = (const float*)d_in[0];
    const float* campos      = (const float*)d_in[1];
    const float* focal       = (const float*)d_in[2];
    const float* princpt     = (const float*)d_in[3];
    const float* pixelcoords = (const float*)d_in[4];
    const float* volume      = (const float*)d_in[5];
    float* out = (float*)d_out;

    const int B = in_sizes[1] / 3;                 // campos: [B,3]
    const int HW = in_sizes[4] / (B * 2);          // pixelcoords: [B,H,W,2]
    int H = 256, W = 256;
    if (HW != H * W) {                              // fallback: square image
        int s = (int)(sqrtf((float)HW) + 0.5f);
        H = s; W = s;
    }

    // 1) transpose volume to interleaved float4 (vectorized)
    {
        int total = (B * D3) / 4;
        int threads = 256;
        int blocks = (total + threads - 1) / threads;
        transpose_vol_kernel<<<blocks, threads>>>(volume);
    }

    // 2) raymarch
    {
        dim3 block(16, 16);
        dim3 grid((W + 15) / 16, (H + 15) / 16, B);
        raymarch_kernel<<<grid, block>>>(camrot, campos, focal, princpt,
                                         pixelcoords, out, H, W);
    }
}